// round 13
// baseline (speedup 1.0000x reference)
#include <cuda_runtime.h>
#include <math.h>

#define T_STEPS 51
#define BATCH   1024
#define SDIM    27
#define HDIM    128
#define EDIM    770
#define DDIM    131
#define ROWS    8
#define NCTA    128
#define NTHR    512
#define STRIDE  912
#define FSTR    272

typedef unsigned long long ull;

// plane-packed weights (same as R11): j = gg*4 + (plane&1)*2 + f/2 ; k = i2*4 + (plane>>1)*2 + (f&1)
__device__ __align__(16) float g_w1t[228*4*128*4];
__device__ __align__(16) float g_wlt[7*64*4*128*4];
__device__ __align__(16) float g_bias[8*512];
__device__ __align__(16) float g_attnT[128*131];
__device__ __align__(16) float g_d1t[68*4*128*4];
__device__ __align__(16) float g_d2t[128*4*64*4];
__device__ __align__(16) float g_d3t[64*4*64*4];
__device__ __align__(16) float g_d4t[64*4*64*4];
__device__ __align__(16) float g_d5t[256*64];

__device__ __forceinline__ void fma2(ull& d, ull a, ull b) {
    asm("fma.rn.f32x2 %0, %1, %2, %0;" : "+l"(d) : "l"(a), "l"(b));
}
__device__ __forceinline__ float unpack_sum(ull a){
    float lo, hi;
    asm("mov.b64 {%0,%1}, %2;" : "=f"(lo), "=f"(hi) : "l"(a));
    return lo + hi;
}
__device__ __forceinline__ float sig_fast(float x){
    return __fdividef(1.f, 1.f + __expf(-x));
}
__device__ __forceinline__ float tanh_fast(float x){
    float t = __expf(-2.f*fabsf(x));
    float y = __fdividef(1.f - t, 1.f + t);
    return copysignf(y, x);
}
#define BAR_A() asm volatile("bar.sync 1, 256;" ::: "memory")
#define BAR_B() asm volatile("bar.sync 2, 256;" ::: "memory")

__device__ __forceinline__ void plane_decode(int i, int JG, int& j, int& k){
    int f = i & 3; int chunk = i >> 2;
    int gg = chunk % JG; int rest = chunk / JG;
    int plane = rest & 3; int i2 = rest >> 2;
    j = gg*4 + ((plane & 1) << 1) + (f >> 1);
    k = i2*4 + ((plane >> 1) << 1) + (f & 1);
}

__global__ void prep_kernel(const float* __restrict__ w_ih1,
                            const float* __restrict__ w_ihr,
                            const float* __restrict__ w_hh,
                            const float* __restrict__ b_ih,
                            const float* __restrict__ b_hh,
                            const float* __restrict__ attn_w,
                            const float* __restrict__ d1_w,
                            const float* __restrict__ d2_w,
                            const float* __restrict__ d3_w,
                            const float* __restrict__ d4_w,
                            const float* __restrict__ d5_w)
{
    int g = blockIdx.x*blockDim.x + threadIdx.x;
    int st = gridDim.x*blockDim.x;
    int j, k;
    for (int i=g; i<228*4*128*4; i+=st){
        plane_decode(i, 128, j, k);
        g_w1t[i] = (k<770) ? w_ih1[j*770+k] :
                   (k<898) ? w_hh[j*128 + (k-770)] : 0.f;
    }
    for (int i=g; i<7*64*4*128*4; i+=st){
        int l = i / (64*4*128*4); int rem = i - l*(64*4*128*4);
        plane_decode(rem, 128, j, k);
        g_wlt[i] = (k<128) ? w_ihr[(l*512+j)*128+k]
                           : w_hh [((l+1)*512+j)*128+(k-128)];
    }
    for (int i=g; i<8*512;  i+=st) g_bias[i] = b_ih[i] + b_hh[i];
    for (int i=g; i<128*131;i+=st){ int kk=i/131, jj=i-kk*131; g_attnT[i]=attn_w[jj*128+kk]; }
    for (int i=g; i<68*4*128*4; i+=st){
        plane_decode(i, 128, j, k);
        g_d1t[i] = (k<259) ? d1_w[j*259+k] : 0.f;
    }
    for (int i=g; i<128*4*64*4; i+=st){
        plane_decode(i, 64, j, k);
        g_d2t[i] = d2_w[j*512+k];
    }
    for (int i=g; i<64*4*64*4; i+=st){
        plane_decode(i, 64, j, k);
        g_d3t[i] = d3_w[j*256+k];
        g_d4t[i] = d4_w[j*256+k];
    }
    for (int i=g; i<256*64; i+=st){ int kk=i>>6, jj=i&63; g_d5t[i]=(jj<51)? d5_w[jj*256+kk] : 0.f; }
}

// GT=4 plane-packed GEMM on a 256-thread group: 8 rows x NOUT, KSLABS=256/(NOUT/4).
template<int NOUT, int SSTR, int I2TOT>
__device__ __forceinline__ void gemm4g(const float* __restrict__ W,
                                       const float* src, float* sP, int lt)
{
    constexpr int JG = NOUT/4;
    constexpr int KSLABS = 256/JG;
    const int kg = lt / JG;
    const int gg = lt - kg*JG;
    const int j0 = gg*4;
    const int i2b = (I2TOT*kg)/KSLABS;
    const int i2e = (I2TOT*(kg+1))/KSLABS;

    ull a0[8], a1[8], a2[8], a3[8];
    #pragma unroll
    for (int r=0;r<8;r++){ a0[r]=0ull; a1[r]=0ull; a2[r]=0ull; a3[r]=0ull; }

    const float* wp = W + (size_t)i2b*(16*JG) + j0;
    for (int i2=i2b; i2<i2e; i2++, wp += 16*JG){
        ulonglong2 wA = *(const ulonglong2*)(wp);
        ulonglong2 wB = *(const ulonglong2*)(wp + 4*JG);
        ulonglong2 wC = *(const ulonglong2*)(wp + 8*JG);
        ulonglong2 wD = *(const ulonglong2*)(wp + 12*JG);
        const float* s0 = src + i2*4;
        #pragma unroll
        for (int r=0;r<8;r++){
            ulonglong2 xx = *(const ulonglong2*)(s0 + r*SSTR);
            fma2(a0[r], wA.x, xx.x);
            fma2(a1[r], wA.y, xx.x);
            fma2(a2[r], wB.x, xx.x);
            fma2(a3[r], wB.y, xx.x);
            fma2(a0[r], wC.x, xx.y);
            fma2(a1[r], wC.y, xx.y);
            fma2(a2[r], wD.x, xx.y);
            fma2(a3[r], wD.y, xx.y);
        }
    }
    float* pr = sP + (kg*8)*NOUT + j0;
    #pragma unroll
    for (int r=0;r<8;r++){
        float4 v = make_float4(unpack_sum(a0[r]), unpack_sum(a1[r]),
                               unpack_sum(a2[r]), unpack_sum(a3[r]));
        *(float4*)(pr + r*NOUT) = v;
    }
}

__global__ void __launch_bounds__(NTHR, 1)
eyet_kernel(const float* __restrict__ dec_emb, const float* __restrict__ enc_out,
            const int*   __restrict__ sp_pos,  const float* __restrict__ attn_b,
            const float* __restrict__ d1_b, const float* __restrict__ d2_b,
            const float* __restrict__ d3_b, const float* __restrict__ d4_b,
            const float* __restrict__ d5_b,
            float* __restrict__ out_loc, float* __restrict__ out_att)
{
    extern __shared__ float sm[];
    float* bufA = sm;                  // [8][912]   layer0 input (group A)
    float* ff0  = sm + 7296;           // [8][272]   feat double buffer
    float* ff1  = ff0 + 2176;
    float* sPA  = ff1 + 2176;          // [16][512]  A partials
    float* sPB  = sPA + 8192;          // [16][512]/[32][256] B partials
    float* sh_h = sPB + 8192;          // [8 rows][8 layers][128]
    float* sh_c = sh_h + 8192;
    float* sh_q = sh_c + 8192;         // [8][132]
    float* bufD = sh_q + 1056;         // [8][512]
    float* bufE = bufD + 4096;         // [8][256]

    const int tid = threadIdx.x;
    const int rowbase = blockIdx.x * ROWS;

    for (int i=tid; i<16384; i+=NTHR) sh_h[i] = 0.f;   // h and c contiguous
    if (tid < 112){                                    // bufA K-pad (898..911)
        int r = tid/14, u = tid - r*14;
        bufA[r*STRIDE + 898 + u] = 0.f;
    }
    __syncthreads();

    for (int t=0; t<=T_STEPS; t++) {
        if (tid < 256 && t < T_STEPS){
            // ===== group A: LSTM + attention for step t =====
            const int lt = tid;
            // stage layer-0 input [x(770) | h0(128) | pad=0]
            for (int r=0;r<ROWS;r++){
                const float* xg = dec_emb + ((size_t)t*BATCH + rowbase + r)*EDIM;
                for (int k=lt; k<EDIM; k+=256) bufA[r*STRIDE + k] = xg[k];
            }
            for (int i=lt; i<ROWS*HDIM; i+=256){
                int r = i>>7, u = i&127;
                bufA[r*STRIDE + EDIM + u] = sh_h[r*1024 + u];
            }
            BAR_A();

            for (int l=0; l<8; l++){
                if (l == 0) gemm4g<512, STRIDE, 228>(g_w1t, bufA, sPA, lt);
                else        gemm4g<512, 1024, 64>(g_wlt + (size_t)(l-1)*(64*4*128*4),
                                                  sh_h + (l-1)*128, sPA, lt);
                BAR_A();
                {   // combine 2 slabs + gates
                    const float* bias = g_bias + l*512;
                    #pragma unroll
                    for (int it=0; it<4; it++){
                        int i = lt + it*256;
                        int r = i>>7, u = i&127;
                        const float* p0 = sPA + r*512;
                        const float* p1 = sPA + (8+r)*512;
                        float gi = p0[u]     + p1[u]     + bias[u];
                        float gf = p0[u+128] + p1[u+128] + bias[u+128];
                        float gc = p0[u+256] + p1[u+256] + bias[u+256];
                        float go = p0[u+384] + p1[u+384] + bias[u+384];
                        int idx = r*1024 + l*128 + u;
                        float c = sig_fast(gf)*sh_c[idx] + sig_fast(gi)*tanh_fast(gc);
                        sh_c[idx] = c;
                        sh_h[idx] = sig_fast(go)*tanh_fast(c);
                    }
                }
                BAR_A();
            }

            // q = ht @ attnT + b (131 threads x 8 rows)
            if (lt < DDIM){
                float acc[8];
                #pragma unroll
                for (int r=0;r<8;r++) acc[r] = 0.f;
                for (int k=0;k<HDIM;k++){
                    float w = g_attnT[k*DDIM + lt];
                    #pragma unroll
                    for (int r=0;r<8;r++) acc[r] += w * sh_h[r*1024 + 896 + k];
                }
                float bb = attn_b[lt];
                #pragma unroll
                for (int r=0;r<8;r++) sh_q[r*132 + lt] = acc[r] + bb;
            }
            BAR_A();

            // windowed attention: warp r handles row r; writes feat ff[t&1]
            {
                float* ffc = (t & 1) ? ff1 : ff0;
                int r = lt >> 5, lane = lt & 31;
                int b = rowbase + r;
                int pos   = sp_pos[b*T_STEPS + t];
                int left  = max(pos-1, 0);
                int right = min(pos+1, SDIM-1);
                int s1i = min(left+1, SDIM-1);
                int s2i = min(left+2, SDIM-1);
                const float* e0p = enc_out + ((size_t)b*SDIM + left)*DDIM;
                const float* e1p = enc_out + ((size_t)b*SDIM + s1i)*DDIM;
                const float* e2p = enc_out + ((size_t)b*SDIM + s2i)*DDIM;
                const float* qv  = sh_q + r*132;

                float s0=0.f, s1=0.f, s2=0.f;
                for (int d=lane; d<DDIM; d+=32){
                    float qd = qv[d];
                    s0 += qd*e0p[d]; s1 += qd*e1p[d]; s2 += qd*e2p[d];
                }
                #pragma unroll
                for (int off=16; off; off>>=1){
                    s0 += __shfl_xor_sync(0xffffffffu, s0, off);
                    s1 += __shfl_xor_sync(0xffffffffu, s1, off);
                    s2 += __shfl_xor_sync(0xffffffffu, s2, off);
                }
                int wsz = right - left;
                float m = fmaxf(s0, s1); if (wsz >= 2) m = fmaxf(m, s2);
                float ex0 = expf(s0 - m);
                float ex1 = expf(s1 - m);
                float ex2 = (wsz >= 2) ? expf(s2 - m) : 0.f;
                float inv = 1.f/(ex0 + ex1 + ex2);
                const float GA = 0.13533528323661270f;   // exp(-2)
                float a0 = ex0*inv * ((left   == pos) ? 1.f : GA);
                float a1 = ex1*inv * ((left+1 == pos) ? 1.f : GA);
                float a2 = ex2*inv * GA;

                for (int d=lane; d<DDIM; d+=32)
                    ffc[r*FSTR + d] = a0*e0p[d] + a1*e1p[d] + a2*e2p[d];
                for (int u=lane; u<HDIM; u+=32)
                    ffc[r*FSTR + DDIM + u] = sh_h[r*1024 + 896 + u];
                if (lane < 13) ffc[r*FSTR + 259 + lane] = 0.f;   // pad 259->272

                if (lane < SDIM){
                    float v = 0.f;
                    if (lane >= left && lane <= right){
                        int i = lane - left;
                        v = (i==0)? a0 : (i==1)? a1 : a2;
                    }
                    out_att[((size_t)b*T_STEPS + t)*SDIM + lane] = v;
                }
            }
        }

        if (tid >= 256 && t > 0){
            // ===== group B: dense head for step t-1 =====
            const int lt = tid - 256;
            const float* fp = ((t-1) & 1) ? ff1 : ff0;

            gemm4g<512, FSTR, 68>(g_d1t, fp, sPB, lt);
            BAR_B();
            #pragma unroll
            for (int it=0; it<16; it++){
                int i = lt + it*256;
                int r = i>>9, j = i&511;
                float v = sPB[r*512+j] + sPB[(8+r)*512+j] + d1_b[j];
                bufD[r*512 + j] = v>0.f ? v : 0.f;
            }
            BAR_B();
            gemm4g<256, 512, 128>(g_d2t, bufD, sPB, lt);
            BAR_B();
            #pragma unroll
            for (int it=0; it<8; it++){
                int i = lt + it*256;
                int r = i>>8, j = i&255;
                float v = d2_b[j];
                #pragma unroll
                for (int s=0;s<4;s++) v += sPB[(s*8+r)*256 + j];
                bufE[r*256 + j] = v>0.f ? v : 0.f;
            }
            BAR_B();
            gemm4g<256, 256, 64>(g_d3t, bufE, sPB, lt);
            BAR_B();
            #pragma unroll
            for (int it=0; it<8; it++){
                int i = lt + it*256;
                int r = i>>8, j = i&255;
                float v = d3_b[j];
                #pragma unroll
                for (int s=0;s<4;s++) v += sPB[(s*8+r)*256 + j];
                bufD[r*256 + j] = v>0.f ? v : 0.f;   // bufD reused as [8][256]
            }
            BAR_B();
            gemm4g<256, 256, 64>(g_d4t, bufD, sPB, lt);
            BAR_B();
            #pragma unroll
            for (int it=0; it<8; it++){
                int i = lt + it*256;
                int r = i>>8, j = i&255;
                float v = d4_b[j];
                #pragma unroll
                for (int s=0;s<4;s++) v += sPB[(s*8+r)*256 + j];
                bufE[r*256 + j] = v>0.f ? v : 0.f;
            }
            BAR_B();

            {   // d5: 8 rows x 51, 2 rows per thread
                int j = lt & 63, rq = lt >> 6;
                if (j < 51){
                    int ra = rq*2, rb = rq*2+1;
                    float s0 = 0.f, s1 = 0.f;
                    const float* xa = bufE + ra*256;
                    const float* xb = bufE + rb*256;
                    for (int k=0;k<256;k++){
                        float w = g_d5t[k*64 + j];
                        s0 += w * xa[k];
                        s1 += w * xb[k];
                    }
                    float bb = d5_b[j];
                    out_loc[((size_t)(rowbase+ra)*T_STEPS + (t-1))*51 + j] = s0 + bb;
                    out_loc[((size_t)(rowbase+rb)*T_STEPS + (t-1))*51 + j] = s1 + bb;
                }
            }
        }
        __syncthreads();   // pipeline handoff: A's ff[t] ready; B done with ff[t-1]
    }
}

static const int SMEM_BYTES = 51616 * (int)sizeof(float);   // 206,464 B

extern "C" void kernel_launch(void* const* d_in, const int* in_sizes, int n_in,
                              void* d_out, int out_size)
{
    (void)in_sizes; (void)n_in; (void)out_size;
    const float* dec    = (const float*)d_in[0];
    const float* enc    = (const float*)d_in[1];
    const int*   sp     = (const int*)  d_in[3];
    const float* w_ih1  = (const float*)d_in[4];
    const float* w_ihr  = (const float*)d_in[5];
    const float* w_hh   = (const float*)d_in[6];
    const float* b_ih   = (const float*)d_in[7];
    const float* b_hh   = (const float*)d_in[8];
    const float* attn_w = (const float*)d_in[9];
    const float* attn_b = (const float*)d_in[10];
    const float* d1w=(const float*)d_in[11]; const float* d1b=(const float*)d_in[12];
    const float* d2w=(const float*)d_in[13]; const float* d2b=(const float*)d_in[14];
    const float* d3w=(const float*)d_in[15]; const float* d3b=(const float*)d_in[16];
    const float* d4w=(const float*)d_in[17]; const float* d4b=(const float*)d_in[18];
    const float* d5w=(const float*)d_in[19]; const float* d5b=(const float*)d_in[20];

    float* out_loc = (float*)d_out;
    float* out_att = out_loc + (size_t)BATCH*T_STEPS*51;

    cudaFuncSetAttribute(eyet_kernel, cudaFuncAttributeMaxDynamicSharedMemorySize, SMEM_BYTES);

    prep_kernel<<<256, 256>>>(w_ih1, w_ihr, w_hh, b_ih, b_hh, attn_w,
                              d1w, d2w, d3w, d4w, d5w);
    eyet_kernel<<<NCTA, NTHR, SMEM_BYTES>>>(dec, enc, sp, attn_b,
                                            d1b, d2b, d3b, d4b, d5b,
                                            out_loc, out_att);
}

// round 16
// speedup vs baseline: 1.3751x; 1.3751x over previous
#include <cuda_runtime.h>
#include <math.h>

#define T_STEPS 51
#define BATCH   1024
#define SDIM    27
#define HDIM    128
#define EDIM    770
#define DDIM    131
#define ROWS    8
#define NCTA    128
#define NTHR    512
#define STRIDE  912

typedef unsigned long long ull;

// plane-packed weights: j = gg*4 + (plane&1)*2 + f/2 ; k = i2*4 + (plane>>1)*2 + (f&1)
__device__ __align__(16) float g_w1t[228*4*128*4];   // K padded 898->912
__device__ __align__(16) float g_wlt[7*64*4*128*4];  // K=256
__device__ __align__(16) float g_bias[8*512];
__device__ __align__(16) float g_attnT[128*131];
__device__ __align__(16) float g_d1t[68*4*128*4];    // K padded 259->272
__device__ __align__(16) float g_d2t[128*4*64*4];    // K=512, NOUT=256
__device__ __align__(16) float g_d3t[64*4*64*4];
__device__ __align__(16) float g_d4t[64*4*64*4];
__device__ __align__(16) float g_d5t[256*64];

__device__ __forceinline__ void fma2(ull& d, ull a, ull b) {
    asm("fma.rn.f32x2 %0, %1, %2, %0;" : "+l"(d) : "l"(a), "l"(b));
}
__device__ __forceinline__ float unpack_sum(ull a){
    float lo, hi;
    asm("mov.b64 {%0,%1}, %2;" : "=f"(lo), "=f"(hi) : "l"(a));
    return lo + hi;
}
__device__ __forceinline__ float sig_fast(float x){
    return __fdividef(1.f, 1.f + __expf(-x));
}
__device__ __forceinline__ float tanh_fast(float x){
    float t = __expf(-2.f*fabsf(x));
    float y = __fdividef(1.f - t, 1.f + t);
    return copysignf(y, x);
}

__device__ __forceinline__ void plane_decode(int i, int JG, int& j, int& k){
    int f = i & 3; int chunk = i >> 2;
    int gg = chunk % JG; int rest = chunk / JG;
    int plane = rest & 3; int i2 = rest >> 2;
    j = gg*4 + ((plane & 1) << 1) + (f >> 1);
    k = i2*4 + ((plane >> 1) << 1) + (f & 1);
}

__global__ void prep_kernel(const float* __restrict__ w_ih1,
                            const float* __restrict__ w_ihr,
                            const float* __restrict__ w_hh,
                            const float* __restrict__ b_ih,
                            const float* __restrict__ b_hh,
                            const float* __restrict__ attn_w,
                            const float* __restrict__ d1_w,
                            const float* __restrict__ d2_w,
                            const float* __restrict__ d3_w,
                            const float* __restrict__ d4_w,
                            const float* __restrict__ d5_w)
{
    int g = blockIdx.x*blockDim.x + threadIdx.x;
    int st = gridDim.x*blockDim.x;
    int j, k;
    for (int i=g; i<228*4*128*4; i+=st){
        plane_decode(i, 128, j, k);
        g_w1t[i] = (k<770) ? w_ih1[j*770+k] :
                   (k<898) ? w_hh[j*128 + (k-770)] : 0.f;
    }
    for (int i=g; i<7*64*4*128*4; i+=st){
        int l = i / (64*4*128*4); int rem = i - l*(64*4*128*4);
        plane_decode(rem, 128, j, k);
        g_wlt[i] = (k<128) ? w_ihr[(l*512+j)*128+k]
                           : w_hh [((l+1)*512+j)*128+(k-128)];
    }
    for (int i=g; i<8*512;  i+=st) g_bias[i] = b_ih[i] + b_hh[i];
    for (int i=g; i<128*131;i+=st){ int kk=i/131, jj=i-kk*131; g_attnT[i]=attn_w[jj*128+kk]; }
    for (int i=g; i<68*4*128*4; i+=st){
        plane_decode(i, 128, j, k);
        g_d1t[i] = (k<259) ? d1_w[j*259+k] : 0.f;
    }
    for (int i=g; i<128*4*64*4; i+=st){
        plane_decode(i, 64, j, k);
        g_d2t[i] = d2_w[j*512+k];
    }
    for (int i=g; i<64*4*64*4; i+=st){
        plane_decode(i, 64, j, k);
        g_d3t[i] = d3_w[j*256+k];
        g_d4t[i] = d4_w[j*256+k];
    }
    for (int i=g; i<256*64; i+=st){ int kk=i>>6, jj=i&63; g_d5t[i]=(jj<51)? d5_w[jj*256+kk] : 0.f; }
}

// GT=4 plane-packed GEMM with register double-buffered weight prefetch.
// 8 rows x NOUT, KSLABS k-slabs, 4 j per thread. sP[(kg*8 + r)*NOUT + j]
template<int NOUT, int SSTR, int I2TOT, int KSLABS>
__device__ __forceinline__ void gemm4(const float* __restrict__ W,
                                      const float* src, float* sP, int tid)
{
    constexpr int JG = NOUT/4;
    const int kg = tid / JG;
    const int gg = tid - kg*JG;
    const int j0 = gg*4;
    const int i2b = (I2TOT*kg)/KSLABS;
    const int i2e = (I2TOT*(kg+1))/KSLABS;

    ull a0[8], a1[8], a2[8], a3[8];
    #pragma unroll
    for (int r=0;r<8;r++){ a0[r]=0ull; a1[r]=0ull; a2[r]=0ull; a3[r]=0ull; }

    const float* wp = W + (size_t)i2b*(16*JG) + j0;
    // prefetch first weight batch
    ulonglong2 wA = *(const ulonglong2*)(wp);
    ulonglong2 wB = *(const ulonglong2*)(wp + 4*JG);
    ulonglong2 wC = *(const ulonglong2*)(wp + 8*JG);
    ulonglong2 wD = *(const ulonglong2*)(wp + 12*JG);

    for (int i2=i2b; i2<i2e-1; i2++){
        wp += 16*JG;
        ulonglong2 nA = *(const ulonglong2*)(wp);
        ulonglong2 nB = *(const ulonglong2*)(wp + 4*JG);
        ulonglong2 nC = *(const ulonglong2*)(wp + 8*JG);
        ulonglong2 nD = *(const ulonglong2*)(wp + 12*JG);
        const float* s0 = src + i2*4;
        #pragma unroll
        for (int r=0;r<8;r++){
            ulonglong2 xx = *(const ulonglong2*)(s0 + r*SSTR);
            fma2(a0[r], wA.x, xx.x);
            fma2(a1[r], wA.y, xx.x);
            fma2(a2[r], wB.x, xx.x);
            fma2(a3[r], wB.y, xx.x);
            fma2(a0[r], wC.x, xx.y);
            fma2(a1[r], wC.y, xx.y);
            fma2(a2[r], wD.x, xx.y);
            fma2(a3[r], wD.y, xx.y);
        }
        wA = nA; wB = nB; wC = nC; wD = nD;
    }
    {   // epilogue: last iteration
        const float* s0 = src + (i2e-1)*4;
        #pragma unroll
        for (int r=0;r<8;r++){
            ulonglong2 xx = *(const ulonglong2*)(s0 + r*SSTR);
            fma2(a0[r], wA.x, xx.x);
            fma2(a1[r], wA.y, xx.x);
            fma2(a2[r], wB.x, xx.x);
            fma2(a3[r], wB.y, xx.x);
            fma2(a0[r], wC.x, xx.y);
            fma2(a1[r], wC.y, xx.y);
            fma2(a2[r], wD.x, xx.y);
            fma2(a3[r], wD.y, xx.y);
        }
    }
    float* pr = sP + (kg*8)*NOUT + j0;
    #pragma unroll
    for (int r=0;r<8;r++){
        float4 v = make_float4(unpack_sum(a0[r]), unpack_sum(a1[r]),
                               unpack_sum(a2[r]), unpack_sum(a3[r]));
        *(float4*)(pr + r*NOUT) = v;
    }
}

// combine 4 k-slabs (NOUT=512) + bias, LSTM gates, update h/c ([r][l][128])
__device__ __forceinline__ void lstm_combine(const float* sP, const float* __restrict__ bias,
                                             float* sh_h, float* sh_c, int l, int tid)
{
    #pragma unroll
    for (int it=0; it<2; it++){
        int i = tid + it*NTHR;
        int r = i>>7, u = i&127;
        const float* p0 = sP + r*512;
        const float* p1 = sP + (8+r)*512;
        const float* p2 = sP + (16+r)*512;
        const float* p3 = sP + (24+r)*512;
        float gi = p0[u]     + p1[u]     + p2[u]     + p3[u]     + bias[u];
        float gf = p0[u+128] + p1[u+128] + p2[u+128] + p3[u+128] + bias[u+128];
        float gc = p0[u+256] + p1[u+256] + p2[u+256] + p3[u+256] + bias[u+256];
        float go = p0[u+384] + p1[u+384] + p2[u+384] + p3[u+384] + bias[u+384];
        int idx = r*1024 + l*128 + u;
        float c = sig_fast(gf)*sh_c[idx] + sig_fast(gi)*tanh_fast(gc);
        sh_c[idx] = c;
        sh_h[idx] = sig_fast(go)*tanh_fast(c);
    }
}

__device__ __forceinline__ void comb4_relu512(const float* sP, const float* __restrict__ bias,
                                              float* dst, int tid)
{
    #pragma unroll
    for (int it=0; it<8; it++){
        int i = tid + it*NTHR;
        int r = i>>9, j = i&511;
        float v = sP[r*512+j] + sP[(8+r)*512+j] + sP[(16+r)*512+j] + sP[(24+r)*512+j] + bias[j];
        dst[r*512 + j] = v>0.f ? v : 0.f;
    }
}
__device__ __forceinline__ void comb8_relu256(const float* sP, const float* __restrict__ bias,
                                              float* dst, int tid)
{
    #pragma unroll
    for (int it=0; it<4; it++){
        int i = tid + it*NTHR;
        int r = i>>8, j = i&255;
        float v = bias[j];
        #pragma unroll
        for (int s=0;s<8;s++) v += sP[(s*8+r)*256 + j];
        dst[r*256 + j] = v>0.f ? v : 0.f;
    }
}

__global__ void __launch_bounds__(NTHR, 1)
eyet_kernel(const float* __restrict__ dec_emb, const float* __restrict__ enc_out,
            const int*   __restrict__ sp_pos,  const float* __restrict__ attn_b,
            const float* __restrict__ d1_b, const float* __restrict__ d2_b,
            const float* __restrict__ d3_b, const float* __restrict__ d4_b,
            const float* __restrict__ d5_b,
            float* __restrict__ out_loc, float* __restrict__ out_att)
{
    extern __shared__ float sm[];
    float* bufA = sm;                       // [8][912]   layer0 input / feat
    float* sP   = sm + 7296;                // [<=64 rows][<=512] GEMM partials (16384)
    float* sh_h = sm + 7296 + 16384;        // [8 rows][8 layers][128]
    float* sh_c = sh_h + 8192;
    float* sh_q = sh_c + 8192;              // [8][132]
    float* bufD = sh_q + 1056;              // [8][512]
    float* bufE = bufD + 4096;              // [8][256]

    const int tid = threadIdx.x;
    const int rowbase = blockIdx.x * ROWS;

    for (int i=tid; i<16384; i+=NTHR) sh_h[i] = 0.f;   // h and c contiguous
    if (tid < 112){                                    // bufA K-pad (898..911)
        int r = tid/14, u = tid - r*14;
        bufA[r*STRIDE + 898 + u] = 0.f;
    }
    __syncthreads();

    for (int t=0; t<T_STEPS; t++) {
        // stage layer-0 input [x(770) | h0(128) | pad(14)=0]
        for (int r=0;r<ROWS;r++){
            const float* xg = dec_emb + ((size_t)t*BATCH + rowbase + r)*EDIM;
            for (int k=tid; k<EDIM; k+=NTHR) bufA[r*STRIDE + k] = xg[k];
        }
        for (int i=tid; i<ROWS*HDIM; i+=NTHR){
            int r = i>>7, u = i&127;
            bufA[r*STRIDE + EDIM + u] = sh_h[r*1024 + u];
        }
        __syncthreads();

        gemm4<512, STRIDE, 228, 4>(g_w1t, bufA, sP, tid);
        __syncthreads();
        lstm_combine(sP, g_bias, sh_h, sh_c, 0, tid);
        __syncthreads();
        for (int l=1; l<8; l++){
            gemm4<512, 1024, 64, 4>(g_wlt + (size_t)(l-1)*(64*4*128*4), sh_h + (l-1)*128, sP, tid);
            __syncthreads();
            lstm_combine(sP, g_bias + l*512, sh_h, sh_c, l, tid);
            __syncthreads();
        }

        // q = ht @ attnT + b   (ht = sh_h[r][7][:])
        if (tid < 262){
            int half = tid >= 131 ? 1 : 0;
            int j = tid - half*131;
            int rb = half*4;
            float acc[4] = {0.f,0.f,0.f,0.f};
            for (int k=0;k<HDIM;k++){
                float w = g_attnT[k*DDIM + j];
                #pragma unroll
                for (int q=0;q<4;q++) acc[q] += w * sh_h[(rb+q)*1024 + 896 + k];
            }
            float bb = attn_b[j];
            #pragma unroll
            for (int q=0;q<4;q++) sh_q[(rb+q)*132 + j] = acc[q] + bb;
        }
        __syncthreads();

        // windowed attention: one warp per row (warps 0-7)
        if (tid < 256){
            int r = tid >> 5, lane = tid & 31;
            int b = rowbase + r;
            int pos   = sp_pos[b*T_STEPS + t];
            int left  = max(pos-1, 0);
            int right = min(pos+1, SDIM-1);
            int s1i = min(left+1, SDIM-1);
            int s2i = min(left+2, SDIM-1);
            const float* e0p = enc_out + ((size_t)b*SDIM + left)*DDIM;
            const float* e1p = enc_out + ((size_t)b*SDIM + s1i)*DDIM;
            const float* e2p = enc_out + ((size_t)b*SDIM + s2i)*DDIM;
            const float* qv  = sh_q + r*132;

            float s0=0.f, s1=0.f, s2=0.f;
            for (int d=lane; d<DDIM; d+=32){
                float qd = qv[d];
                s0 += qd*e0p[d]; s1 += qd*e1p[d]; s2 += qd*e2p[d];
            }
            #pragma unroll
            for (int off=16; off; off>>=1){
                s0 += __shfl_xor_sync(0xffffffffu, s0, off);
                s1 += __shfl_xor_sync(0xffffffffu, s1, off);
                s2 += __shfl_xor_sync(0xffffffffu, s2, off);
            }
            int wsz = right - left;
            float m = fmaxf(s0, s1); if (wsz >= 2) m = fmaxf(m, s2);
            float ex0 = expf(s0 - m);
            float ex1 = expf(s1 - m);
            float ex2 = (wsz >= 2) ? expf(s2 - m) : 0.f;
            float inv = 1.f/(ex0 + ex1 + ex2);
            const float GA = 0.13533528323661270f;   // exp(-2)
            float a0 = ex0*inv * ((left   == pos) ? 1.f : GA);
            float a1 = ex1*inv * ((left+1 == pos) ? 1.f : GA);
            float a2 = ex2*inv * GA;

            for (int d=lane; d<DDIM; d+=32)
                bufA[r*STRIDE + d] = a0*e0p[d] + a1*e1p[d] + a2*e2p[d];
            for (int u=lane; u<HDIM; u+=32)
                bufA[r*STRIDE + DDIM + u] = sh_h[r*1024 + 896 + u];
            if (lane < 13) bufA[r*STRIDE + 259 + lane] = 0.f;   // pad K 259->272

            if (lane < SDIM){
                float v = 0.f;
                if (lane >= left && lane <= right){
                    int i = lane - left;
                    v = (i==0)? a0 : (i==1)? a1 : a2;
                }
                out_att[((size_t)b*T_STEPS + t)*SDIM + lane] = v;
            }
        }
        __syncthreads();

        // dense head
        gemm4<512, STRIDE, 68, 4>(g_d1t, bufA, sP, tid);
        __syncthreads();
        comb4_relu512(sP, d1_b, bufD, tid);
        __syncthreads();
        gemm4<256, 512, 128, 8>(g_d2t, bufD, sP, tid);
        __syncthreads();
        comb8_relu256(sP, d2_b, bufE, tid);
        __syncthreads();
        gemm4<256, 256, 64, 8>(g_d3t, bufE, sP, tid);
        __syncthreads();
        comb8_relu256(sP, d3_b, bufD, tid);     // bufD reused as [8][256]
        __syncthreads();
        gemm4<256, 256, 64, 8>(g_d4t, bufD, sP, tid);
        __syncthreads();
        comb8_relu256(sP, d4_b, bufE, tid);
        __syncthreads();

        {   // d5: 8 rows x 51, one thread per (r,j)
            int j = tid & 63, r = tid >> 6;
            if (j < 51){
                float a = 0.f;
                const float* xr = bufE + r*256;
                for (int k=0;k<256;k++) a += g_d5t[k*64 + j] * xr[k];
                out_loc[((size_t)(rowbase+r)*T_STEPS + t)*51 + j] = a + d5_b[j];
            }
        }
        __syncthreads();
    }
}

static const int SMEM_BYTES = (7296 + 16384 + 8192 + 8192 + 1056 + 4096 + 2048) * (int)sizeof(float);

extern "C" void kernel_launch(void* const* d_in, const int* in_sizes, int n_in,
                              void* d_out, int out_size)
{
    (void)in_sizes; (void)n_in; (void)out_size;
    const float* dec    = (const float*)d_in[0];
    const float* enc    = (const float*)d_in[1];
    const int*   sp     = (const int*)  d_in[3];
    const float* w_ih1  = (const float*)d_in[4];
    const float* w_ihr  = (const float*)d_in[5];
    const float* w_hh   = (const float*)d_in[6];
    const float* b_ih   = (const float*)d_in[7];
    const float* b_hh   = (const float*)d_in[8];
    const float* attn_w = (const float*)d_in[9];
    const float* attn_b = (const float*)d_in[10];
    const float* d1w=(const float*)d_in[11]; const float* d1b=(const float*)d_in[12];
    const float* d2w=(const float*)d_in[13]; const float* d2b=(const float*)d_in[14];
    const float* d3w=(const float*)d_in[15]; const float* d3b=(const float*)d_in[16];
    const float* d4w=(const float*)d_in[17]; const float* d4b=(const float*)d_in[18];
    const float* d5w=(const float*)d_in[19]; const float* d5b=(const float*)d_in[20];

    float* out_loc = (float*)d_out;
    float* out_att = out_loc + (size_t)BATCH*T_STEPS*51;

    cudaFuncSetAttribute(eyet_kernel, cudaFuncAttributeMaxDynamicSharedMemorySize, SMEM_BYTES);

    prep_kernel<<<256, 256>>>(w_ih1, w_ihr, w_hh, b_ih, b_hh, attn_w,
                              d1w, d2w, d3w, d4w, d5w);
    eyet_kernel<<<NCTA, NTHR, SMEM_BYTES>>>(dec, enc, sp, attn_b,
                                            d1b, d2b, d3b, d4b, d5b,
                                            out_loc, out_att);
}